// round 6
// baseline (speedup 1.0000x reference)
#include <cuda_runtime.h>
#include <cuda_bf16.h>

#define BIG 1e4f
#define IMH 1024
#define IMW 1024

constexpr int TY     = 64;                // output rows per warp
constexpr int NSEG   = 8;                 // 1024/128 horizontal warp segments
constexpr int NSTRIP = IMH / TY;          // 16
constexpr int NTHREADS = 256;             // 8 warps / block
// total warps = 24*16*8 = 3072 -> 384 blocks, single resident wave

// Unconditional (clamped) load of the 8-wide window of row q, pad applied after.
__device__ __forceinline__ void load_row(const float* __restrict__ pbase, int q,
                                         int offL, int offR, bool padL, bool padR,
                                         float w[8])
{
    int qc = q < 0 ? 0 : (q >= IMH ? IMH - 1 : q);
    const float* p = pbase + (size_t)qc * IMW;
    float4 v  = *reinterpret_cast<const float4*>(p);
    float2 lv = *reinterpret_cast<const float2*>(p + offL);
    float2 rv = *reinterpret_cast<const float2*>(p + offR);
    if (padL) { lv.x = BIG; lv.y = BIG; }
    if (padR) { rv.x = BIG; rv.y = BIG; }
    w[0]=lv.x; w[1]=lv.y; w[2]=v.x; w[3]=v.y; w[4]=v.z; w[5]=v.w; w[6]=rv.x; w[7]=rv.y;
    if (q < 0 || q >= IMH) {
#pragma unroll
        for (int k = 0; k < 8; k++) w[k] = BIG;
    }
}

template<bool CROSS>
__device__ __forceinline__ void run_warp(const float* __restrict__ src,
                                         float*       __restrict__ dst,
                                         const int* km, int x0, int y0)
{
    float eA[6], eB[6];   // erosion accumulators: rows q-1, q
    float dA[4], dB[4];   // dilation accumulators: rows q-2, q-1
#pragma unroll
    for (int k = 0; k < 6; k++) { eA[k] = BIG; eB[k] = BIG; }
#pragma unroll
    for (int k = 0; k < 4; k++) { dA[k] = -BIG; dB[k] = -BIG; }

    const bool xlo = (x0 == 0);              // eroded pos x0-1 == -1
    const bool xhi = (x0 == IMW - 4);        // eroded pos x0+4 == IMW
    const int  offL = (x0 >= 2)       ? -2 : 0;
    const int  offR = (x0 <= IMW - 8) ?  4 : 0;
    const bool padL = (x0 < 2);
    const bool padR = (x0 > IMW - 8);
    const float* __restrict__ pbase = src + x0;

    // ---- software pipeline: wA = row q, wB = row q+1 ----
    float wA[8], wB[8];
    load_row(pbase, y0 - 2, offL, offR, padL, padR, wA);
    load_row(pbase, y0 - 1, offL, offR, padL, padR, wB);

#pragma unroll 4
    for (int q = y0 - 2; q <= y0 + TY + 1; q++) {
        // prefetch row q+2 (unconditional, clamped; unused tail rows harmless)
        float wN[8];
        load_row(pbase, q + 2, offL, offR, padL, padR, wN);

        const float* w = wA;   // window of row q, loaded 2 iterations ago

        // ---- erosion contributions of input row q (6-wide: x0-1..x0+4) ----
        float eC[6];
        if (CROSS) {
#pragma unroll
            for (int k = 0; k < 6; k++) {
                float h = fminf(fminf(w[k], w[k + 1]), w[k + 2]);
                eC[k] = w[k + 1];               // mask row 0: center only
                eB[k] = fminf(eB[k], h);        // mask row 1: full
                eA[k] = fminf(eA[k], w[k + 1]); // mask row 2: center only
            }
        } else {
            float c0[6], c1[6], c2[6];
#pragma unroll
            for (int k = 0; k < 6; k++) { c0[k] = BIG; c1[k] = BIG; c2[k] = BIG; }
#pragma unroll
            for (int j = 0; j < 3; j++) {
                if (km[0*3 + j]) {
#pragma unroll
                    for (int k = 0; k < 6; k++) c0[k] = fminf(c0[k], w[k + j]);
                }
                if (km[1*3 + j]) {
#pragma unroll
                    for (int k = 0; k < 6; k++) c1[k] = fminf(c1[k], w[k + j]);
                }
                if (km[2*3 + j]) {
#pragma unroll
                    for (int k = 0; k < 6; k++) c2[k] = fminf(c2[k], w[k + j]);
                }
            }
#pragma unroll
            for (int k = 0; k < 6; k++) {
                eC[k] = c0[k];
                eB[k] = fminf(eB[k], c1[k]);
                eA[k] = fminf(eA[k], c2[k]);
            }
        }

        // ---- eA complete: eroded row ry = q-1; apply -BIG padding ----
        int ry = q - 1;
        if (ry < 0 || ry >= IMH) {
#pragma unroll
            for (int k = 0; k < 6; k++) eA[k] = -BIG;
        } else {
            if (xlo) eA[0] = -BIG;
            if (xhi) eA[5] = -BIG;
        }

        // ---- dilation contributions of eroded row ry (4-wide) ----
        float dC[4];
        if (CROSS) {
#pragma unroll
            for (int k = 0; k < 4; k++) {
                float g = fmaxf(fmaxf(eA[k], eA[k + 1]), eA[k + 2]);
                dC[k] = eA[k + 1];
                dB[k] = fmaxf(dB[k], g);
                dA[k] = fmaxf(dA[k], eA[k + 1]);
            }
        } else {
            float g0[4], g1[4], g2[4];
#pragma unroll
            for (int k = 0; k < 4; k++) { g0[k] = -BIG; g1[k] = -BIG; g2[k] = -BIG; }
#pragma unroll
            for (int j = 0; j < 3; j++) {
                if (km[0*3 + j]) {
#pragma unroll
                    for (int k = 0; k < 4; k++) g0[k] = fmaxf(g0[k], eA[k + j]);
                }
                if (km[1*3 + j]) {
#pragma unroll
                    for (int k = 0; k < 4; k++) g1[k] = fmaxf(g1[k], eA[k + j]);
                }
                if (km[2*3 + j]) {
#pragma unroll
                    for (int k = 0; k < 4; k++) g2[k] = fmaxf(g2[k], eA[k + j]);
                }
            }
#pragma unroll
            for (int k = 0; k < 4; k++) {
                dC[k] = g0[k];
                dB[k] = fmaxf(dB[k], g1[k]);
                dA[k] = fmaxf(dA[k], g2[k]);
            }
        }

        // ---- dA complete: output row sy = q-2 ----
        if (q >= y0 + 2) {
            int sy = q - 2;
            *reinterpret_cast<float4*>(dst + (size_t)sy * IMW + x0) =
                make_float4(dA[0], dA[1], dA[2], dA[3]);
        }

        // ---- rotate pipelines ----
#pragma unroll
        for (int k = 0; k < 6; k++) { eA[k] = eB[k]; eB[k] = eC[k]; }
#pragma unroll
        for (int k = 0; k < 4; k++) { dA[k] = dB[k]; dB[k] = dC[k]; }
#pragma unroll
        for (int k = 0; k < 8; k++) { wA[k] = wB[k]; wB[k] = wN[k]; }
    }
}

__global__ __launch_bounds__(NTHREADS)
void opening_kernel(const float* __restrict__ img,
                    const int*   __restrict__ ker,
                    float*       __restrict__ out)
{
    int km[9];
#pragma unroll
    for (int i = 0; i < 9; i++) km[i] = ker[i];
    const bool cross = (km[0] == 0) && (km[1] == 1) && (km[2] == 0) &&
                       (km[3] == 1) && (km[4] == 1) && (km[5] == 1) &&
                       (km[6] == 0) && (km[7] == 1) && (km[8] == 0);

    const int gw   = blockIdx.x * (NTHREADS / 32) + (threadIdx.x >> 5);
    const int lane = threadIdx.x & 31;
    const int xseg   = gw & (NSEG - 1);
    const int t      = gw >> 3;               // log2(NSEG)=3
    const int ystrip = t & (NSTRIP - 1);
    const int bc     = t >> 4;                // log2(NSTRIP)=4

    const int x0 = xseg * 128 + lane * 4;
    const int y0 = ystrip * TY;

    const float* src = img + (size_t)bc * (IMH * IMW);
    float*       dst = out + (size_t)bc * (IMH * IMW);

    if (cross) run_warp<true >(src, dst, km, x0, y0);
    else       run_warp<false>(src, dst, km, x0, y0);
}

extern "C" void kernel_launch(void* const* d_in, const int* in_sizes, int n_in,
                              void* d_out, int out_size)
{
    const float* img = (const float*)d_in[0];   // [8,3,1024,1024] fp32
    const int*   ker = (const int*)d_in[1];     // [3,3] int32 mask
    float*       out = (float*)d_out;

    const int BC = in_sizes[0] / (IMH * IMW);   // 24
    const int warps  = BC * NSTRIP * NSEG;      // 3072
    const int blocks = warps / (NTHREADS / 32); // 384
    opening_kernel<<<blocks, NTHREADS>>>(img, ker, out);
}

// round 8
// speedup vs baseline: 1.5797x; 1.5797x over previous
#include <cuda_runtime.h>
#include <cuda_bf16.h>

#define BIG 1e4f
#define IMH 1024
#define IMW 1024

constexpr int TY     = 32;                // output rows per warp
constexpr int NSEG   = 8;                 // 1024/128 horizontal warp segments
constexpr int NSTRIP = IMH / TY;          // 32
constexpr int NTHREADS = 256;             // 8 warps / block
// total warps = 24*32*8 = 6144 -> 768 blocks -> ~41.5 warps/SM of work

template<bool CROSS>
__device__ __forceinline__ void run_warp(const float* __restrict__ src,
                                         float*       __restrict__ dst,
                                         const int* km, int x0, int y0)
{
    float eA[6], eB[6];   // erosion accumulators: rows q-1, q
    float dA[4], dB[4];   // dilation accumulators: rows q-2, q-1
#pragma unroll
    for (int k = 0; k < 6; k++) { eA[k] = BIG; eB[k] = BIG; }
#pragma unroll
    for (int k = 0; k < 4; k++) { dA[k] = -BIG; dB[k] = -BIG; }

    const bool xlo = (x0 == 0);              // eroded pos x0-1 == -1
    const bool xhi = (x0 == IMW - 4);        // eroded pos x0+4 == IMW
    const int  offL = (x0 >= 2)       ? -2 : 0;
    const int  offR = (x0 <= IMW - 8) ?  4 : 0;
    const bool padL = (x0 < 2);
    const bool padR = (x0 > IMW - 8);
    const float* __restrict__ pbase = src + x0;

#pragma unroll 4
    for (int q = y0 - 2; q <= y0 + TY + 1; q++) {
        // ---- unconditional loads from clamped row, then select-pad ----
        int qc = q < 0 ? 0 : (q >= IMH ? IMH - 1 : q);
        const float* p = pbase + (size_t)qc * IMW;
        float4 v  = *reinterpret_cast<const float4*>(p);
        float2 lv = *reinterpret_cast<const float2*>(p + offL);
        float2 rv = *reinterpret_cast<const float2*>(p + offR);
        if (padL) { lv.x = BIG; lv.y = BIG; }
        if (padR) { rv.x = BIG; rv.y = BIG; }
        float w[8];
        w[0]=lv.x; w[1]=lv.y; w[2]=v.x; w[3]=v.y; w[4]=v.z; w[5]=v.w; w[6]=rv.x; w[7]=rv.y;
        if (q < 0 || q >= IMH) {
#pragma unroll
            for (int k = 0; k < 8; k++) w[k] = BIG;
        }

        // ---- erosion contributions of input row q (6-wide: x0-1..x0+4) ----
        float eC[6];
        if (CROSS) {
#pragma unroll
            for (int k = 0; k < 6; k++) {
                float h = fminf(fminf(w[k], w[k + 1]), w[k + 2]);
                eC[k] = w[k + 1];               // mask row 0: center only
                eB[k] = fminf(eB[k], h);        // mask row 1: full
                eA[k] = fminf(eA[k], w[k + 1]); // mask row 2: center only
            }
        } else {
            float c0[6], c1[6], c2[6];
#pragma unroll
            for (int k = 0; k < 6; k++) { c0[k] = BIG; c1[k] = BIG; c2[k] = BIG; }
#pragma unroll
            for (int j = 0; j < 3; j++) {
                if (km[0*3 + j]) {
#pragma unroll
                    for (int k = 0; k < 6; k++) c0[k] = fminf(c0[k], w[k + j]);
                }
                if (km[1*3 + j]) {
#pragma unroll
                    for (int k = 0; k < 6; k++) c1[k] = fminf(c1[k], w[k + j]);
                }
                if (km[2*3 + j]) {
#pragma unroll
                    for (int k = 0; k < 6; k++) c2[k] = fminf(c2[k], w[k + j]);
                }
            }
#pragma unroll
            for (int k = 0; k < 6; k++) {
                eC[k] = c0[k];
                eB[k] = fminf(eB[k], c1[k]);
                eA[k] = fminf(eA[k], c2[k]);
            }
        }

        // ---- eA complete: eroded row ry = q-1; apply -BIG padding ----
        int ry = q - 1;
        if (ry < 0 || ry >= IMH) {
#pragma unroll
            for (int k = 0; k < 6; k++) eA[k] = -BIG;
        } else {
            if (xlo) eA[0] = -BIG;
            if (xhi) eA[5] = -BIG;
        }

        // ---- dilation contributions of eroded row ry (4-wide) ----
        float dC[4];
        if (CROSS) {
#pragma unroll
            for (int k = 0; k < 4; k++) {
                float g = fmaxf(fmaxf(eA[k], eA[k + 1]), eA[k + 2]);
                dC[k] = eA[k + 1];
                dB[k] = fmaxf(dB[k], g);
                dA[k] = fmaxf(dA[k], eA[k + 1]);
            }
        } else {
            float g0[4], g1[4], g2[4];
#pragma unroll
            for (int k = 0; k < 4; k++) { g0[k] = -BIG; g1[k] = -BIG; g2[k] = -BIG; }
#pragma unroll
            for (int j = 0; j < 3; j++) {
                if (km[0*3 + j]) {
#pragma unroll
                    for (int k = 0; k < 4; k++) g0[k] = fmaxf(g0[k], eA[k + j]);
                }
                if (km[1*3 + j]) {
#pragma unroll
                    for (int k = 0; k < 4; k++) g1[k] = fmaxf(g1[k], eA[k + j]);
                }
                if (km[2*3 + j]) {
#pragma unroll
                    for (int k = 0; k < 4; k++) g2[k] = fmaxf(g2[k], eA[k + j]);
                }
            }
#pragma unroll
            for (int k = 0; k < 4; k++) {
                dC[k] = g0[k];
                dB[k] = fmaxf(dB[k], g1[k]);
                dA[k] = fmaxf(dA[k], g2[k]);
            }
        }

        // ---- dA complete: output row sy = q-2 ----
        if (q >= y0 + 2) {
            int sy = q - 2;
            *reinterpret_cast<float4*>(dst + (size_t)sy * IMW + x0) =
                make_float4(dA[0], dA[1], dA[2], dA[3]);
        }

        // ---- rotate pipelines ----
#pragma unroll
        for (int k = 0; k < 6; k++) { eA[k] = eB[k]; eB[k] = eC[k]; }
#pragma unroll
        for (int k = 0; k < 4; k++) { dA[k] = dB[k]; dB[k] = dC[k]; }
    }
}

__global__ __launch_bounds__(NTHREADS)
void opening_kernel(const float* __restrict__ img,
                    const int*   __restrict__ ker,
                    float*       __restrict__ out)
{
    int km[9];
#pragma unroll
    for (int i = 0; i < 9; i++) km[i] = ker[i];
    const bool cross = (km[0] == 0) && (km[1] == 1) && (km[2] == 0) &&
                       (km[3] == 1) && (km[4] == 1) && (km[5] == 1) &&
                       (km[6] == 0) && (km[7] == 1) && (km[8] == 0);

    const int gw   = blockIdx.x * (NTHREADS / 32) + (threadIdx.x >> 5);
    const int lane = threadIdx.x & 31;
    const int xseg   = gw & (NSEG - 1);
    const int t      = gw >> 3;               // log2(NSEG)=3
    const int ystrip = t & (NSTRIP - 1);
    const int bc     = t >> 5;                // log2(NSTRIP)=5

    const int x0 = xseg * 128 + lane * 4;
    const int y0 = ystrip * TY;

    const float* src = img + (size_t)bc * (IMH * IMW);
    float*       dst = out + (size_t)bc * (IMH * IMW);

    if (cross) run_warp<true >(src, dst, km, x0, y0);
    else       run_warp<false>(src, dst, km, x0, y0);
}

extern "C" void kernel_launch(void* const* d_in, const int* in_sizes, int n_in,
                              void* d_out, int out_size)
{
    const float* img = (const float*)d_in[0];   // [8,3,1024,1024] fp32
    const int*   ker = (const int*)d_in[1];     // [3,3] int32 mask
    float*       out = (float*)d_out;

    const int BC = in_sizes[0] / (IMH * IMW);   // 24
    const int warps  = BC * NSTRIP * NSEG;      // 6144
    const int blocks = warps / (NTHREADS / 32); // 768
    opening_kernel<<<blocks, NTHREADS>>>(img, ker, out);
}

// round 11
// speedup vs baseline: 2.3401x; 1.4813x over previous
#include <cuda_runtime.h>
#include <cuda_bf16.h>

#define BIG 1e4f
#define IMH 1024
#define IMW 1024

constexpr int TY      = 32;               // output rows per warp
constexpr int NSEG    = 4;                // 1024/256: warp covers 256 floats
constexpr int NSTRIP  = IMH / TY;         // 32
constexpr int NTHREADS = 256;             // 8 warps / block
// warps = 24*32*4 = 3072 -> 384 blocks -> 20.8 warps/SM, ALL resident (3 blocks/SM)

// ---------------- cross fast path: 8 output columns per lane ----------------
__device__ __forceinline__ void run_warp8_cross(const float* __restrict__ src,
                                                float*       __restrict__ dst,
                                                int x0, int y0)
{
    float eA[10], eB[10];  // erosion rows q-1, q   (x0-1 .. x0+8)
    float dA[8],  dB[8];   // dilation rows q-2, q-1 (x0 .. x0+7)
#pragma unroll
    for (int k = 0; k < 10; k++) { eA[k] = BIG; eB[k] = BIG; }
#pragma unroll
    for (int k = 0; k < 8; k++)  { dA[k] = -BIG; dB[k] = -BIG; }

    const bool xlo  = (x0 == 0);            // eroded pos x0-1 == -1
    const bool xhi  = (x0 == IMW - 8);      // eroded pos x0+8 == IMW
    const int  offL = xlo ? 0 : -2;
    const int  offR = (x0 <= IMW - 10) ? 8 : 0;
    const float* __restrict__ pbase = src + x0;

#pragma unroll 2
    for (int q = y0 - 2; q <= y0 + TY + 1; q++) {
        // ---- unconditional loads from clamped row, select-pad after ----
        int qc = q < 0 ? 0 : (q >= IMH ? IMH - 1 : q);
        const float* p = pbase + (size_t)qc * IMW;
        float4 v0 = *reinterpret_cast<const float4*>(p);
        float4 v1 = *reinterpret_cast<const float4*>(p + 4);
        float2 lv = *reinterpret_cast<const float2*>(p + offL);
        float2 rv = *reinterpret_cast<const float2*>(p + offR);
        if (xlo) { lv.x = BIG; lv.y = BIG; }
        if (xhi) { rv.x = BIG; rv.y = BIG; }
        float w[12];
        w[0]=lv.x; w[1]=lv.y;
        w[2]=v0.x; w[3]=v0.y; w[4]=v0.z; w[5]=v0.w;
        w[6]=v1.x; w[7]=v1.y; w[8]=v1.z; w[9]=v1.w;
        w[10]=rv.x; w[11]=rv.y;
        if (q < 0 || q >= IMH) {
#pragma unroll
            for (int k = 0; k < 12; k++) w[k] = BIG;
        }

        // ---- erosion contributions of input row q (10-wide) ----
        float eC[10];
#pragma unroll
        for (int k = 0; k < 10; k++) {
            float h = fminf(fminf(w[k], w[k + 1]), w[k + 2]);
            eC[k] = w[k + 1];               // mask row 0: center only
            eB[k] = fminf(eB[k], h);        // mask row 1: full
            eA[k] = fminf(eA[k], w[k + 1]); // mask row 2: center only
        }

        // ---- eA complete: eroded row ry = q-1; -BIG padding ----
        int ry = q - 1;
        if (ry < 0 || ry >= IMH) {
#pragma unroll
            for (int k = 0; k < 10; k++) eA[k] = -BIG;
        } else {
            if (xlo) eA[0] = -BIG;
            if (xhi) eA[9] = -BIG;
        }

        // ---- dilation contributions of eroded row ry (8-wide) ----
        float dC[8];
#pragma unroll
        for (int k = 0; k < 8; k++) {
            float g = fmaxf(fmaxf(eA[k], eA[k + 1]), eA[k + 2]);
            dC[k] = eA[k + 1];
            dB[k] = fmaxf(dB[k], g);
            dA[k] = fmaxf(dA[k], eA[k + 1]);
        }

        // ---- dA complete: output row sy = q-2 ----
        if (q >= y0 + 2) {
            int sy = q - 2;
            float* o = dst + (size_t)sy * IMW + x0;
            *reinterpret_cast<float4*>(o)     = make_float4(dA[0], dA[1], dA[2], dA[3]);
            *reinterpret_cast<float4*>(o + 4) = make_float4(dA[4], dA[5], dA[6], dA[7]);
        }

        // ---- rotate pipelines ----
#pragma unroll
        for (int k = 0; k < 10; k++) { eA[k] = eB[k]; eB[k] = eC[k]; }
#pragma unroll
        for (int k = 0; k < 8; k++)  { dA[k] = dB[k]; dB[k] = dC[k]; }
    }
}

// ---------------- generic-mask fallback: 4 columns per call ----------------
__device__ void run_warp4_generic(const float* __restrict__ src,
                                  float*       __restrict__ dst,
                                  const int* km, int x0, int y0)
{
    float eA[6], eB[6];
    float dA[4], dB[4];
#pragma unroll
    for (int k = 0; k < 6; k++) { eA[k] = BIG; eB[k] = BIG; }
#pragma unroll
    for (int k = 0; k < 4; k++) { dA[k] = -BIG; dB[k] = -BIG; }

    const bool xlo = (x0 == 0);
    const bool xhi = (x0 == IMW - 4);
    const int  offL = (x0 >= 2)       ? -2 : 0;
    const int  offR = (x0 <= IMW - 8) ?  4 : 0;
    const bool padL = (x0 < 2);
    const bool padR = (x0 > IMW - 8);
    const float* __restrict__ pbase = src + x0;

    for (int q = y0 - 2; q <= y0 + TY + 1; q++) {
        int qc = q < 0 ? 0 : (q >= IMH ? IMH - 1 : q);
        const float* p = pbase + (size_t)qc * IMW;
        float4 v  = *reinterpret_cast<const float4*>(p);
        float2 lv = *reinterpret_cast<const float2*>(p + offL);
        float2 rv = *reinterpret_cast<const float2*>(p + offR);
        if (padL) { lv.x = BIG; lv.y = BIG; }
        if (padR) { rv.x = BIG; rv.y = BIG; }
        float w[8];
        w[0]=lv.x; w[1]=lv.y; w[2]=v.x; w[3]=v.y; w[4]=v.z; w[5]=v.w; w[6]=rv.x; w[7]=rv.y;
        if (q < 0 || q >= IMH) {
#pragma unroll
            for (int k = 0; k < 8; k++) w[k] = BIG;
        }

        float c0[6], c1[6], c2[6];
#pragma unroll
        for (int k = 0; k < 6; k++) { c0[k] = BIG; c1[k] = BIG; c2[k] = BIG; }
#pragma unroll
        for (int j = 0; j < 3; j++) {
            if (km[0*3 + j]) {
#pragma unroll
                for (int k = 0; k < 6; k++) c0[k] = fminf(c0[k], w[k + j]);
            }
            if (km[1*3 + j]) {
#pragma unroll
                for (int k = 0; k < 6; k++) c1[k] = fminf(c1[k], w[k + j]);
            }
            if (km[2*3 + j]) {
#pragma unroll
                for (int k = 0; k < 6; k++) c2[k] = fminf(c2[k], w[k + j]);
            }
        }
        float eC[6];
#pragma unroll
        for (int k = 0; k < 6; k++) {
            eC[k] = c0[k];
            eB[k] = fminf(eB[k], c1[k]);
            eA[k] = fminf(eA[k], c2[k]);
        }

        int ry = q - 1;
        if (ry < 0 || ry >= IMH) {
#pragma unroll
            for (int k = 0; k < 6; k++) eA[k] = -BIG;
        } else {
            if (xlo) eA[0] = -BIG;
            if (xhi) eA[5] = -BIG;
        }

        float g0[4], g1[4], g2[4];
#pragma unroll
        for (int k = 0; k < 4; k++) { g0[k] = -BIG; g1[k] = -BIG; g2[k] = -BIG; }
#pragma unroll
        for (int j = 0; j < 3; j++) {
            if (km[0*3 + j]) {
#pragma unroll
                for (int k = 0; k < 4; k++) g0[k] = fmaxf(g0[k], eA[k + j]);
            }
            if (km[1*3 + j]) {
#pragma unroll
                for (int k = 0; k < 4; k++) g1[k] = fmaxf(g1[k], eA[k + j]);
            }
            if (km[2*3 + j]) {
#pragma unroll
                for (int k = 0; k < 4; k++) g2[k] = fmaxf(g2[k], eA[k + j]);
            }
        }
        float dC[4];
#pragma unroll
        for (int k = 0; k < 4; k++) {
            dC[k] = g0[k];
            dB[k] = fmaxf(dB[k], g1[k]);
            dA[k] = fmaxf(dA[k], g2[k]);
        }

        if (q >= y0 + 2) {
            int sy = q - 2;
            *reinterpret_cast<float4*>(dst + (size_t)sy * IMW + x0) =
                make_float4(dA[0], dA[1], dA[2], dA[3]);
        }

#pragma unroll
        for (int k = 0; k < 6; k++) { eA[k] = eB[k]; eB[k] = eC[k]; }
#pragma unroll
        for (int k = 0; k < 4; k++) { dA[k] = dB[k]; dB[k] = dC[k]; }
    }
}

__global__ __launch_bounds__(NTHREADS, 3)
void opening_kernel(const float* __restrict__ img,
                    const int*   __restrict__ ker,
                    float*       __restrict__ out)
{
    int km[9];
#pragma unroll
    for (int i = 0; i < 9; i++) km[i] = ker[i];
    const bool cross = (km[0] == 0) && (km[1] == 1) && (km[2] == 0) &&
                       (km[3] == 1) && (km[4] == 1) && (km[5] == 1) &&
                       (km[6] == 0) && (km[7] == 1) && (km[8] == 0);

    const int gw   = blockIdx.x * (NTHREADS / 32) + (threadIdx.x >> 5);
    const int lane = threadIdx.x & 31;
    const int xseg   = gw & (NSEG - 1);       // 2 bits
    const int t      = gw >> 2;
    const int ystrip = t & (NSTRIP - 1);      // 5 bits
    const int bc     = t >> 5;

    const int x0 = xseg * 256 + lane * 8;
    const int y0 = ystrip * TY;

    const float* src = img + (size_t)bc * (IMH * IMW);
    float*       dst = out + (size_t)bc * (IMH * IMW);

    if (cross) {
        run_warp8_cross(src, dst, x0, y0);
    } else {
        run_warp4_generic(src, dst, km, x0,     y0);
        run_warp4_generic(src, dst, km, x0 + 4, y0);
    }
}

extern "C" void kernel_launch(void* const* d_in, const int* in_sizes, int n_in,
                              void* d_out, int out_size)
{
    const float* img = (const float*)d_in[0];   // [8,3,1024,1024] fp32
    const int*   ker = (const int*)d_in[1];     // [3,3] int32 mask
    float*       out = (float*)d_out;

    const int BC = in_sizes[0] / (IMH * IMW);   // 24
    const int warps  = BC * NSTRIP * NSEG;      // 3072
    const int blocks = warps / (NTHREADS / 32); // 384
    opening_kernel<<<blocks, NTHREADS>>>(img, ker, out);
}